// round 10
// baseline (speedup 1.0000x reference)
#include <cuda_runtime.h>
#include <cstdint>

#define N_NODES 100000
#define E_MAX   1700000
#define F_IN    128
#define F_HID   64
#define F_OUT   32
#define SCAN_TPB 1024
#define SCAN_NB  ((N_NODES + SCAN_TPB - 1) / SCAN_TPB)   // 98

// Scratch (no allocations allowed). Referenced ONLY from device code.
__device__ float g_h[N_NODES * F_HID];     // h1 = x@W1
__device__ float g_h2[N_NODES * F_HID];    // relu(gcn1)
__device__ float g_dinv[N_NODES];          // 1/sqrt(deg)
__device__ int   g_count[N_NODES];         // in-degree (excl. self-loop)
__device__ int   g_cursor[N_NODES];        // fill cursors (seeded = rowstart)
__device__ int   g_rowstart[N_NODES + 1];  // CSR row offsets (by dst)
__device__ int   g_adj[E_MAX];             // src ids grouped by dst
__device__ int   g_partial[SCAN_NB];       // per-block sums for scan
__device__ int   g_is32;                   // 1 if edge_index is int32

// ---------------------------------------------------------------------------
// index readers (uniform branch on detected dtype)
// ---------------------------------------------------------------------------
__device__ __forceinline__ int read_idx(const void* ei, int E, int row, int e,
                                        int is32) {
    if (is32)  return ((const int*)ei)[(size_t)row * E + e];
    else       return (int)((const long long*)ei)[(size_t)row * E + e];
}

// ---------------------------------------------------------------------------
// 1. init + dtype detect fused.
//    int64 node ids (< 1e5) have zero high-32 bits in every 8B word;
//    packed int32 pairs have nonzero high half whenever idx[2t+1] != 0.
// ---------------------------------------------------------------------------
__global__ void initdetect_kernel(const unsigned long long* __restrict__ ei,
                                  int E) {
    int i = blockIdx.x * blockDim.x + threadIdx.x;
    if (i < N_NODES) g_count[i] = 0;
    if (i == 0) g_is32 = 0;
    int limit = (E < 2048) ? E : 2048;
    if (i < limit) {
        if (ei[i] > 0xFFFFFFFFULL) atomicExch(&g_is32, 1);
    }
}

// ---------------------------------------------------------------------------
// 2. histogram of dst (scalar int atomics only)
// ---------------------------------------------------------------------------
__global__ void hist_kernel(const void* __restrict__ ei, int E) {
    int e = blockIdx.x * blockDim.x + threadIdx.x;
    if (e >= E) return;
    int d = read_idx(ei, E, 1, e, g_is32);
    atomicAdd(&g_count[d], 1);
}

// ---------------------------------------------------------------------------
// 3a. scan phase A: per-block reduction of counts -> g_partial[b]
// ---------------------------------------------------------------------------
__global__ void scanA_kernel() {
    __shared__ int sh[32];
    int i = blockIdx.x * SCAN_TPB + threadIdx.x;
    int v = (i < N_NODES) ? g_count[i] : 0;
    #pragma unroll
    for (int o = 16; o > 0; o >>= 1) v += __shfl_down_sync(0xFFFFFFFFu, v, o);
    int lane = threadIdx.x & 31, warp = threadIdx.x >> 5;
    if (lane == 0) sh[warp] = v;
    __syncthreads();
    if (warp == 0) {
        v = (lane < SCAN_TPB / 32) ? sh[lane] : 0;
        #pragma unroll
        for (int o = 16; o > 0; o >>= 1) v += __shfl_down_sync(0xFFFFFFFFu, v, o);
        if (lane == 0) g_partial[blockIdx.x] = v;
    }
}

// ---------------------------------------------------------------------------
// 3b. scan phase C: each block redundantly scans the 98 partials itself
//     (kills the separate scanB launch), then does its local scan.
//     Writes rowstart, cursor (=rowstart), dinv.
// ---------------------------------------------------------------------------
__global__ void scanC_kernel() {
    __shared__ int sh[SCAN_TPB];
    __shared__ int off[128];
    int t = threadIdx.x;

    // inline exclusive scan of the 98 block partials
    int raw = 0;
    if (t < 128) {
        raw = (t < SCAN_NB) ? g_partial[t] : 0;
        off[t] = raw;
    }
    __syncthreads();
    for (int o = 1; o < 128; o <<= 1) {
        int u = 0;
        if (t < 128 && t >= o) u = off[t - o];
        __syncthreads();
        if (t < 128) off[t] += u;
        __syncthreads();
    }
    // off[] now inclusive; exclusive offset for block b = off[b] - raw_b
    // (only need this block's offset and the grand total)
    __shared__ int blk_off, total;
    if (t == blockIdx.x) blk_off = off[t] - raw;
    if (t == 127) total = off[127];
    __syncthreads();

    // local scan of counts
    int i = blockIdx.x * SCAN_TPB + t;
    int c = (i < N_NODES) ? g_count[i] : 0;
    sh[t] = c;
    __syncthreads();
    for (int o = 1; o < SCAN_TPB; o <<= 1) {
        int u = (t >= o) ? sh[t - o] : 0;
        __syncthreads();
        sh[t] += u;
        __syncthreads();
    }
    if (i < N_NODES) {
        int rs = blk_off + sh[t] - c;                 // exclusive
        g_rowstart[i] = rs;
        g_cursor[i]   = rs;                           // seed fill cursor
        g_dinv[i] = rsqrtf((float)c + 1.0f);
    }
    if (blockIdx.x == 0 && t == 0) g_rowstart[N_NODES] = total;
}

// ---------------------------------------------------------------------------
// 4. FUSED fill + gemm1 (independent work, overlapped in one launch).
//    blocks [0, nfill)          : fill adjacency
//    blocks [nfill, nfill+ngemm): h = x @ W1, 16 rows per block
// ---------------------------------------------------------------------------
__global__ void fillgemm_kernel(const void* __restrict__ ei, int E, int nfill,
                                const float* __restrict__ x,
                                const float* __restrict__ W1) {
    int tid = threadIdx.x;

    if ((int)blockIdx.x < nfill) {
        // ----- fill path -----
        int e = blockIdx.x * blockDim.x + tid;
        if (e >= E) return;
        int is32 = g_is32;
        int sidx = read_idx(ei, E, 0, e, is32);
        int d    = read_idx(ei, E, 1, e, is32);
        int pos = atomicAdd(&g_cursor[d], 1);      // absolute position
        g_adj[pos] = sidx;
    } else {
        // ----- gemm path: 16 rows/block -----
        __shared__ float Ws[F_IN * F_HID];   // 32 KB
        __shared__ float xs[16][F_IN];       // 8 KB

        for (int i = tid; i < F_IN * F_HID; i += 256) Ws[i] = W1[i];

        int row0 = ((int)blockIdx.x - nfill) * 16;
        for (int i = tid; i < 16 * F_IN; i += 256) {
            int r = i >> 7, k = i & 127;
            int row = row0 + r;
            xs[r][k] = (row < N_NODES) ? x[(size_t)row * F_IN + k] : 0.0f;
        }
        __syncthreads();

        int col = tid & 63;
        int rg  = tid >> 6;          // 0..3 -> rows rg*4 .. rg*4+3
        int rbase = rg * 4;
        float acc0 = 0.f, acc1 = 0.f, acc2 = 0.f, acc3 = 0.f;
    #pragma unroll
        for (int k = 0; k < F_IN; k++) {
            float w = Ws[k * F_HID + col];
            acc0 = fmaf(xs[rbase + 0][k], w, acc0);
            acc1 = fmaf(xs[rbase + 1][k], w, acc1);
            acc2 = fmaf(xs[rbase + 2][k], w, acc2);
            acc3 = fmaf(xs[rbase + 3][k], w, acc3);
        }
        int row = row0 + rbase;
        if (row + 0 < N_NODES) g_h[(size_t)(row + 0) * F_HID + col] = acc0;
        if (row + 1 < N_NODES) g_h[(size_t)(row + 1) * F_HID + col] = acc1;
        if (row + 2 < N_NODES) g_h[(size_t)(row + 2) * F_HID + col] = acc2;
        if (row + 3 < N_NODES) g_h[(size_t)(row + 3) * F_HID + col] = acc3;
    }
}

// ---------------------------------------------------------------------------
// aggregation core (R8 proven form): 16 lanes per node, lane owns 4 features
// (float4), edge loop unrolled x4.
// ---------------------------------------------------------------------------
__device__ __forceinline__ float4 agg_node(const float* __restrict__ in,
                                           int node, int fo) {
    float di = g_dinv[node];
    float4 v = *reinterpret_cast<const float4*>(&in[(size_t)node * F_HID + fo]);
    float dd = di * di;
    float ax = dd * v.x, ay = dd * v.y, az = dd * v.z, aw = dd * v.w;

    int beg = g_rowstart[node];
    int end = g_rowstart[node + 1];

    int j = beg;
    for (; j + 3 < end; j += 4) {
        int s0 = g_adj[j + 0];
        int s1 = g_adj[j + 1];
        int s2 = g_adj[j + 2];
        int s3 = g_adj[j + 3];
        float c0 = g_dinv[s0] * di;
        float c1 = g_dinv[s1] * di;
        float c2 = g_dinv[s2] * di;
        float c3 = g_dinv[s3] * di;
        float4 h0 = *reinterpret_cast<const float4*>(&in[(size_t)s0 * F_HID + fo]);
        float4 h1 = *reinterpret_cast<const float4*>(&in[(size_t)s1 * F_HID + fo]);
        float4 h2 = *reinterpret_cast<const float4*>(&in[(size_t)s2 * F_HID + fo]);
        float4 h3 = *reinterpret_cast<const float4*>(&in[(size_t)s3 * F_HID + fo]);
        ax = fmaf(c0, h0.x, ax); ay = fmaf(c0, h0.y, ay);
        az = fmaf(c0, h0.z, az); aw = fmaf(c0, h0.w, aw);
        ax = fmaf(c1, h1.x, ax); ay = fmaf(c1, h1.y, ay);
        az = fmaf(c1, h1.z, az); aw = fmaf(c1, h1.w, aw);
        ax = fmaf(c2, h2.x, ax); ay = fmaf(c2, h2.y, ay);
        az = fmaf(c2, h2.z, az); aw = fmaf(c2, h2.w, aw);
        ax = fmaf(c3, h3.x, ax); ay = fmaf(c3, h3.y, ay);
        az = fmaf(c3, h3.z, az); aw = fmaf(c3, h3.w, aw);
    }
    for (; j < end; j++) {
        int s = g_adj[j];
        float c = g_dinv[s] * di;
        float4 hv = *reinterpret_cast<const float4*>(&in[(size_t)s * F_HID + fo]);
        ax = fmaf(c, hv.x, ax); ay = fmaf(c, hv.y, ay);
        az = fmaf(c, hv.z, az); aw = fmaf(c, hv.w, aw);
    }
    return make_float4(ax, ay, az, aw);
}

// ---------------------------------------------------------------------------
// 5. pass-1 aggregate + bias + relu -> g_h2
// ---------------------------------------------------------------------------
__global__ void agg1_kernel(const float* __restrict__ b1) {
    int tid    = threadIdx.x;            // 256 threads = 16 nodes/block
    int group  = tid >> 4;
    int lane16 = tid & 15;
    int node = blockIdx.x * 16 + group;
    if (node >= N_NODES) return;

    int fo = lane16 * 4;
    float4 a = agg_node(g_h, node, fo);

    float4 bb = *reinterpret_cast<const float4*>(&b1[fo]);
    a.x += bb.x; a.y += bb.y; a.z += bb.z; a.w += bb.w;
    a.x = a.x > 0.f ? a.x : 0.f;
    a.y = a.y > 0.f ? a.y : 0.f;
    a.z = a.z > 0.f ? a.z : 0.f;
    a.w = a.w > 0.f ? a.w : 0.f;
    *reinterpret_cast<float4*>(&g_h2[(size_t)node * F_HID + fo]) = a;
}

// ---------------------------------------------------------------------------
// 6. FUSED pass-2 aggregate + dual output GEMM.
// ---------------------------------------------------------------------------
__global__ void agg2_out_kernel(const float* __restrict__ Wmu,
                                const float* __restrict__ bmu,
                                const float* __restrict__ Wls,
                                const float* __restrict__ bls,
                                float* __restrict__ out) {
    __shared__ float Wm[F_HID * F_OUT];  // 8 KB
    __shared__ float Wl[F_HID * F_OUT];  // 8 KB
    __shared__ float hs[16][F_HID];      // 4 KB

    int tid = threadIdx.x;               // 0..255
    for (int i = tid; i < F_HID * F_OUT; i += 256) { Wm[i] = Wmu[i]; Wl[i] = Wls[i]; }

    int node0 = blockIdx.x * 16;

    // Phase A: aggregation (16 lanes per node, float4 per lane)
    {
        int group  = tid >> 4;
        int lane16 = tid & 15;
        int node = node0 + group;
        if (node < N_NODES) {
            int fo = lane16 * 4;
            float4 a = agg_node(g_h2, node, fo);
            *reinterpret_cast<float4*>(&hs[group][fo]) = a;
        }
    }
    __syncthreads();

    // Phase B: dual GEMM, warp per node (2 nodes per warp via stride-8 loop)
    int warp = tid >> 5, lane = tid & 31;
    float bm = bmu[lane];
    float bl = bls[lane];
    #pragma unroll
    for (int nn = warp; nn < 16; nn += 8) {
        int node = node0 + nn;
        if (node >= N_NODES) continue;
        float am = bm;
        float al = bl;
        #pragma unroll
        for (int f = 0; f < F_HID; f++) {
            float hv = hs[nn][f];
            am = fmaf(hv, Wm[f * F_OUT + lane], am);
            al = fmaf(hv, Wl[f * F_OUT + lane], al);
        }
        out[(size_t)node * F_OUT + lane] = am;
        out[(size_t)N_NODES * F_OUT + (size_t)node * F_OUT + lane] = al;
    }
}

// ---------------------------------------------------------------------------
// launch — everything on cudaStreamPerThread so graph capture records it
// ---------------------------------------------------------------------------
extern "C" void kernel_launch(void* const* d_in, const int* in_sizes, int n_in,
                              void* d_out, int out_size) {
    const float* x   = (const float*)d_in[0];
    const void*  ei  = d_in[1];                    // [2, E], int32 OR int64
    const float* W1  = (const float*)d_in[2];
    const float* b1  = (const float*)d_in[3];
    const float* Wmu = (const float*)d_in[4];
    const float* bmu = (const float*)d_in[5];
    const float* Wls = (const float*)d_in[6];
    const float* bls = (const float*)d_in[7];
    float*       out = (float*)d_out;

    const int E = in_sizes[1] / 2;
    const int T = 256;
    cudaStream_t s = cudaStreamPerThread;

    const int nfill = (E + T - 1) / T;
    const int ngemm = (N_NODES + 15) / 16;

    initdetect_kernel<<<(N_NODES + T - 1) / T, T, 0, s>>>(
        (const unsigned long long*)ei, E);
    hist_kernel<<<(E + T - 1) / T, T, 0, s>>>(ei, E);
    scanA_kernel<<<SCAN_NB, SCAN_TPB, 0, s>>>();
    scanC_kernel<<<SCAN_NB, SCAN_TPB, 0, s>>>();
    fillgemm_kernel<<<nfill + ngemm, T, 0, s>>>(ei, E, nfill, x, W1);
    agg1_kernel<<<(N_NODES + 15) / 16, T, 0, s>>>(b1);
    agg2_out_kernel<<<(N_NODES + 15) / 16, T, 0, s>>>(Wmu, bmu, Wls, bls, out);
}

// round 11
// speedup vs baseline: 1.1081x; 1.1081x over previous
#include <cuda_runtime.h>
#include <cuda_fp16.h>
#include <cstdint>

#define N_NODES 100000
#define E_MAX   1700000
#define F_IN    128
#define F_HID   64
#define F_OUT   32
#define SCAN_TPB 1024
#define SCAN_NB  ((N_NODES + SCAN_TPB - 1) / SCAN_TPB)   // 98

// Scratch (no allocations allowed). Referenced ONLY from device code.
// Feature rows stored fp16: 64 * 2B = 128B = one cache line per node row.
__device__ __half g_h[N_NODES * F_HID];    // h1 = x@W1          (fp16)
__device__ __half g_h2[N_NODES * F_HID];   // relu(gcn1)         (fp16)
__device__ float  g_dinv[N_NODES];         // 1/sqrt(deg)
__device__ int    g_count[N_NODES];        // in-degree (excl. self-loop)
__device__ int    g_cursor[N_NODES];       // fill cursors (seeded = rowstart)
__device__ int    g_rowstart[N_NODES + 1]; // CSR row offsets (by dst)
__device__ int    g_adj[E_MAX];            // src ids grouped by dst
__device__ int    g_partial[SCAN_NB];      // per-block sums for scan
__device__ int    g_is32;                  // 1 if edge_index is int32

// ---------------------------------------------------------------------------
// fp16 pack/unpack helpers (4 features <-> uint2)
// ---------------------------------------------------------------------------
__device__ __forceinline__ float4 h4_to_f4(uint2 u) {
    __half2 a = *reinterpret_cast<__half2*>(&u.x);
    __half2 b = *reinterpret_cast<__half2*>(&u.y);
    float2 fa = __half22float2(a), fb = __half22float2(b);
    return make_float4(fa.x, fa.y, fb.x, fb.y);
}
__device__ __forceinline__ uint2 f4_to_h4(float4 v) {
    __half2 a = __floats2half2_rn(v.x, v.y);
    __half2 b = __floats2half2_rn(v.z, v.w);
    uint2 u;
    u.x = *reinterpret_cast<uint32_t*>(&a);
    u.y = *reinterpret_cast<uint32_t*>(&b);
    return u;
}

// ---------------------------------------------------------------------------
// index readers (uniform branch on detected dtype)
// ---------------------------------------------------------------------------
__device__ __forceinline__ int read_idx(const void* ei, int E, int row, int e,
                                        int is32) {
    if (is32)  return ((const int*)ei)[(size_t)row * E + e];
    else       return (int)((const long long*)ei)[(size_t)row * E + e];
}

// ---------------------------------------------------------------------------
// 1. init + dtype detect fused.
// ---------------------------------------------------------------------------
__global__ void initdetect_kernel(const unsigned long long* __restrict__ ei,
                                  int E) {
    int i = blockIdx.x * blockDim.x + threadIdx.x;
    if (i < N_NODES) g_count[i] = 0;
    if (i == 0) g_is32 = 0;
    int limit = (E < 2048) ? E : 2048;
    if (i < limit) {
        if (ei[i] > 0xFFFFFFFFULL) atomicExch(&g_is32, 1);
    }
}

// ---------------------------------------------------------------------------
// 2. histogram of dst (scalar int atomics only)
// ---------------------------------------------------------------------------
__global__ void hist_kernel(const void* __restrict__ ei, int E) {
    int e = blockIdx.x * blockDim.x + threadIdx.x;
    if (e >= E) return;
    int d = read_idx(ei, E, 1, e, g_is32);
    atomicAdd(&g_count[d], 1);
}

// ---------------------------------------------------------------------------
// 3a. scan phase A: per-block reduction of counts -> g_partial[b]
// ---------------------------------------------------------------------------
__global__ void scanA_kernel() {
    __shared__ int sh[32];
    int i = blockIdx.x * SCAN_TPB + threadIdx.x;
    int v = (i < N_NODES) ? g_count[i] : 0;
    #pragma unroll
    for (int o = 16; o > 0; o >>= 1) v += __shfl_down_sync(0xFFFFFFFFu, v, o);
    int lane = threadIdx.x & 31, warp = threadIdx.x >> 5;
    if (lane == 0) sh[warp] = v;
    __syncthreads();
    if (warp == 0) {
        v = (lane < SCAN_TPB / 32) ? sh[lane] : 0;
        #pragma unroll
        for (int o = 16; o > 0; o >>= 1) v += __shfl_down_sync(0xFFFFFFFFu, v, o);
        if (lane == 0) g_partial[blockIdx.x] = v;
    }
}

// ---------------------------------------------------------------------------
// 3b. scan phase C: each block inlines the scan of the 98 partials, then
//     local scan. Writes rowstart, cursor (=rowstart), dinv.
// ---------------------------------------------------------------------------
__global__ void scanC_kernel() {
    __shared__ int sh[SCAN_TPB];
    __shared__ int off[128];
    int t = threadIdx.x;

    int raw = 0;
    if (t < 128) {
        raw = (t < SCAN_NB) ? g_partial[t] : 0;
        off[t] = raw;
    }
    __syncthreads();
    for (int o = 1; o < 128; o <<= 1) {
        int u = 0;
        if (t < 128 && t >= o) u = off[t - o];
        __syncthreads();
        if (t < 128) off[t] += u;
        __syncthreads();
    }
    __shared__ int blk_off, total;
    if (t == blockIdx.x) blk_off = off[t] - raw;
    if (t == 127) total = off[127];
    __syncthreads();

    int i = blockIdx.x * SCAN_TPB + t;
    int c = (i < N_NODES) ? g_count[i] : 0;
    sh[t] = c;
    __syncthreads();
    for (int o = 1; o < SCAN_TPB; o <<= 1) {
        int u = (t >= o) ? sh[t - o] : 0;
        __syncthreads();
        sh[t] += u;
        __syncthreads();
    }
    if (i < N_NODES) {
        int rs = blk_off + sh[t] - c;                 // exclusive
        g_rowstart[i] = rs;
        g_cursor[i]   = rs;                           // seed fill cursor
        g_dinv[i] = rsqrtf((float)c + 1.0f);
    }
    if (blockIdx.x == 0 && t == 0) g_rowstart[N_NODES] = total;
}

// ---------------------------------------------------------------------------
// 4. fill adjacency (src ids grouped by dst; cursor pre-seeded to rowstart)
// ---------------------------------------------------------------------------
__global__ void fill_kernel(const void* __restrict__ ei, int E) {
    int e = blockIdx.x * blockDim.x + threadIdx.x;
    if (e >= E) return;
    int is32 = g_is32;
    int sidx = read_idx(ei, E, 0, e, is32);
    int d    = read_idx(ei, E, 1, e, is32);
    int pos = atomicAdd(&g_cursor[d], 1);   // absolute position
    g_adj[pos] = sidx;
}

// ---------------------------------------------------------------------------
// 5. g_h = fp16(x @ W1)   (N x 128) @ (128 x 64); 32 rows/block, 256 threads.
// ---------------------------------------------------------------------------
__global__ void gemm1_kernel(const float* __restrict__ x,
                             const float* __restrict__ W1) {
    __shared__ float Ws[F_IN * F_HID];   // 32 KB
    __shared__ float xs[32][F_IN];       // 16 KB

    int tid = threadIdx.x;               // 0..255
    for (int i = tid; i < F_IN * F_HID; i += 256) Ws[i] = W1[i];

    int row0 = blockIdx.x * 32;
    for (int i = tid; i < 32 * F_IN; i += 256) {
        int r = i >> 7, k = i & 127;
        int row = row0 + r;
        xs[r][k] = (row < N_NODES) ? x[(size_t)row * F_IN + k] : 0.0f;
    }
    __syncthreads();

    int col = tid & 63;
    int rg  = tid >> 6;                  // 0..3 -> rows rg*8 .. rg*8+7
    int rbase = rg * 8;
    float acc[8];
    #pragma unroll
    for (int r = 0; r < 8; r++) acc[r] = 0.0f;

#pragma unroll
    for (int k = 0; k < F_IN; k++) {
        float w = Ws[k * F_HID + col];
        #pragma unroll
        for (int r = 0; r < 8; r++) acc[r] = fmaf(xs[rbase + r][k], w, acc[r]);
    }
    #pragma unroll
    for (int r = 0; r < 8; r++) {
        int row = row0 + rbase + r;
        if (row < N_NODES) g_h[(size_t)row * F_HID + col] = __float2half(acc[r]);
    }
}

// ---------------------------------------------------------------------------
// aggregation core: 16 lanes per node, lane owns 4 fp16 features (uint2 = 8B).
// A full node row = 128B = one cache line. fp32 accumulation.
// Edge loop unrolled x4 (R8 proven structure).
// ---------------------------------------------------------------------------
__device__ __forceinline__ float4 agg_node(const __half* __restrict__ in,
                                           int node, int fo) {
    float di = g_dinv[node];
    float4 v = h4_to_f4(*reinterpret_cast<const uint2*>(&in[(size_t)node * F_HID + fo]));
    float dd = di * di;
    float ax = dd * v.x, ay = dd * v.y, az = dd * v.z, aw = dd * v.w;

    int beg = g_rowstart[node];
    int end = g_rowstart[node + 1];

    int j = beg;
    for (; j + 3 < end; j += 4) {
        int s0 = g_adj[j + 0];
        int s1 = g_adj[j + 1];
        int s2 = g_adj[j + 2];
        int s3 = g_adj[j + 3];
        float c0 = g_dinv[s0] * di;
        float c1 = g_dinv[s1] * di;
        float c2 = g_dinv[s2] * di;
        float c3 = g_dinv[s3] * di;
        uint2 r0 = *reinterpret_cast<const uint2*>(&in[(size_t)s0 * F_HID + fo]);
        uint2 r1 = *reinterpret_cast<const uint2*>(&in[(size_t)s1 * F_HID + fo]);
        uint2 r2 = *reinterpret_cast<const uint2*>(&in[(size_t)s2 * F_HID + fo]);
        uint2 r3 = *reinterpret_cast<const uint2*>(&in[(size_t)s3 * F_HID + fo]);
        float4 h0 = h4_to_f4(r0);
        float4 h1 = h4_to_f4(r1);
        float4 h2 = h4_to_f4(r2);
        float4 h3 = h4_to_f4(r3);
        ax = fmaf(c0, h0.x, ax); ay = fmaf(c0, h0.y, ay);
        az = fmaf(c0, h0.z, az); aw = fmaf(c0, h0.w, aw);
        ax = fmaf(c1, h1.x, ax); ay = fmaf(c1, h1.y, ay);
        az = fmaf(c1, h1.z, az); aw = fmaf(c1, h1.w, aw);
        ax = fmaf(c2, h2.x, ax); ay = fmaf(c2, h2.y, ay);
        az = fmaf(c2, h2.z, az); aw = fmaf(c2, h2.w, aw);
        ax = fmaf(c3, h3.x, ax); ay = fmaf(c3, h3.y, ay);
        az = fmaf(c3, h3.z, az); aw = fmaf(c3, h3.w, aw);
    }
    for (; j < end; j++) {
        int s = g_adj[j];
        float c = g_dinv[s] * di;
        float4 hv = h4_to_f4(*reinterpret_cast<const uint2*>(&in[(size_t)s * F_HID + fo]));
        ax = fmaf(c, hv.x, ax); ay = fmaf(c, hv.y, ay);
        az = fmaf(c, hv.z, az); aw = fmaf(c, hv.w, aw);
    }
    return make_float4(ax, ay, az, aw);
}

// ---------------------------------------------------------------------------
// 6. pass-1 aggregate + bias + relu -> g_h2 (fp16)
// ---------------------------------------------------------------------------
__global__ void agg1_kernel(const float* __restrict__ b1) {
    int tid    = threadIdx.x;            // 256 threads = 16 nodes/block
    int group  = tid >> 4;
    int lane16 = tid & 15;
    int node = blockIdx.x * 16 + group;
    if (node >= N_NODES) return;

    int fo = lane16 * 4;
    float4 a = agg_node(g_h, node, fo);

    float4 bb = *reinterpret_cast<const float4*>(&b1[fo]);
    a.x += bb.x; a.y += bb.y; a.z += bb.z; a.w += bb.w;
    a.x = a.x > 0.f ? a.x : 0.f;
    a.y = a.y > 0.f ? a.y : 0.f;
    a.z = a.z > 0.f ? a.z : 0.f;
    a.w = a.w > 0.f ? a.w : 0.f;
    *reinterpret_cast<uint2*>(&g_h2[(size_t)node * F_HID + fo]) = f4_to_h4(a);
}

// ---------------------------------------------------------------------------
// 7. FUSED pass-2 aggregate + dual output GEMM.
// ---------------------------------------------------------------------------
__global__ void agg2_out_kernel(const float* __restrict__ Wmu,
                                const float* __restrict__ bmu,
                                const float* __restrict__ Wls,
                                const float* __restrict__ bls,
                                float* __restrict__ out) {
    __shared__ float Wm[F_HID * F_OUT];  // 8 KB
    __shared__ float Wl[F_HID * F_OUT];  // 8 KB
    __shared__ float hs[16][F_HID];      // 4 KB

    int tid = threadIdx.x;               // 0..255
    for (int i = tid; i < F_HID * F_OUT; i += 256) { Wm[i] = Wmu[i]; Wl[i] = Wls[i]; }

    int node0 = blockIdx.x * 16;

    // Phase A: aggregation (16 lanes per node, 4 fp16 features per lane)
    {
        int group  = tid >> 4;
        int lane16 = tid & 15;
        int node = node0 + group;
        if (node < N_NODES) {
            int fo = lane16 * 4;
            float4 a = agg_node(g_h2, node, fo);
            *reinterpret_cast<float4*>(&hs[group][fo]) = a;
        }
    }
    __syncthreads();

    // Phase B: dual GEMM, warp per node (2 nodes per warp via stride-8 loop)
    int warp = tid >> 5, lane = tid & 31;
    float bm = bmu[lane];
    float bl = bls[lane];
    #pragma unroll
    for (int nn = warp; nn < 16; nn += 8) {
        int node = node0 + nn;
        if (node >= N_NODES) continue;
        float am = bm;
        float al = bl;
        #pragma unroll
        for (int f = 0; f < F_HID; f++) {
            float hv = hs[nn][f];
            am = fmaf(hv, Wm[f * F_OUT + lane], am);
            al = fmaf(hv, Wl[f * F_OUT + lane], al);
        }
        out[(size_t)node * F_OUT + lane] = am;
        out[(size_t)N_NODES * F_OUT + (size_t)node * F_OUT + lane] = al;
    }
}

// ---------------------------------------------------------------------------
// launch — everything on cudaStreamPerThread so graph capture records it
// ---------------------------------------------------------------------------
extern "C" void kernel_launch(void* const* d_in, const int* in_sizes, int n_in,
                              void* d_out, int out_size) {
    const float* x   = (const float*)d_in[0];
    const void*  ei  = d_in[1];                    // [2, E], int32 OR int64
    const float* W1  = (const float*)d_in[2];
    const float* b1  = (const float*)d_in[3];
    const float* Wmu = (const float*)d_in[4];
    const float* bmu = (const float*)d_in[5];
    const float* Wls = (const float*)d_in[6];
    const float* bls = (const float*)d_in[7];
    float*       out = (float*)d_out;

    const int E = in_sizes[1] / 2;
    const int T = 256;
    cudaStream_t s = cudaStreamPerThread;

    initdetect_kernel<<<(N_NODES + T - 1) / T, T, 0, s>>>(
        (const unsigned long long*)ei, E);
    hist_kernel<<<(E + T - 1) / T, T, 0, s>>>(ei, E);
    scanA_kernel<<<SCAN_NB, SCAN_TPB, 0, s>>>();
    scanC_kernel<<<SCAN_NB, SCAN_TPB, 0, s>>>();
    fill_kernel<<<(E + T - 1) / T, T, 0, s>>>(ei, E);
    gemm1_kernel<<<(N_NODES + 31) / 32, T, 0, s>>>(x, W1);
    agg1_kernel<<<(N_NODES + 15) / 16, T, 0, s>>>(b1);
    agg2_out_kernel<<<(N_NODES + 15) / 16, T, 0, s>>>(Wmu, bmu, Wls, bls, out);
}

// round 12
// speedup vs baseline: 1.1744x; 1.0598x over previous
#include <cuda_runtime.h>
#include <cuda_fp16.h>
#include <cstdint>

#define N_NODES 100000
#define E_MAX   1700000
#define F_IN    128
#define F_HID   64
#define F_OUT   32
#define SCAN_TPB 1024
#define SCAN_NB  ((N_NODES + SCAN_TPB - 1) / SCAN_TPB)   // 98

// Scratch (no allocations allowed). Referenced ONLY from device code.
// Feature rows stored fp16: 64 * 2B = 128B = one cache line per node row.
__device__ __half g_h[N_NODES * F_HID];    // h1 = x@W1          (fp16)
__device__ __half g_h2[N_NODES * F_HID];   // relu(gcn1)         (fp16)
__device__ float  g_dinv[N_NODES];         // 1/sqrt(deg)
__device__ int    g_count[N_NODES];        // in-degree (excl. self-loop)
__device__ int    g_cursor[N_NODES];       // fill cursors (seeded = rowstart)
__device__ int    g_rowstart[N_NODES + 1]; // CSR row offsets (by dst)
__device__ int    g_adj[E_MAX];            // src ids grouped by dst
__device__ int    g_partial[SCAN_NB];      // per-block sums for scan
__device__ int    g_is32;                  // 1 if edge_index is int32

// ---------------------------------------------------------------------------
// fp16 pack/unpack helpers (4 features <-> uint2)
// ---------------------------------------------------------------------------
__device__ __forceinline__ float4 h4_to_f4(uint2 u) {
    __half2 a = *reinterpret_cast<__half2*>(&u.x);
    __half2 b = *reinterpret_cast<__half2*>(&u.y);
    float2 fa = __half22float2(a), fb = __half22float2(b);
    return make_float4(fa.x, fa.y, fb.x, fb.y);
}
__device__ __forceinline__ uint2 f4_to_h4(float4 v) {
    __half2 a = __floats2half2_rn(v.x, v.y);
    __half2 b = __floats2half2_rn(v.z, v.w);
    uint2 u;
    u.x = *reinterpret_cast<uint32_t*>(&a);
    u.y = *reinterpret_cast<uint32_t*>(&b);
    return u;
}

// ---------------------------------------------------------------------------
// index readers (uniform branch on detected dtype)
// ---------------------------------------------------------------------------
__device__ __forceinline__ int read_idx(const void* ei, int E, int row, int e,
                                        int is32) {
    if (is32)  return ((const int*)ei)[(size_t)row * E + e];
    else       return (int)((const long long*)ei)[(size_t)row * E + e];
}

// ---------------------------------------------------------------------------
// 1. init + dtype detect fused.
// ---------------------------------------------------------------------------
__global__ void initdetect_kernel(const unsigned long long* __restrict__ ei,
                                  int E) {
    int i = blockIdx.x * blockDim.x + threadIdx.x;
    if (i < N_NODES) g_count[i] = 0;
    if (i == 0) g_is32 = 0;
    int limit = (E < 2048) ? E : 2048;
    if (i < limit) {
        if (ei[i] > 0xFFFFFFFFULL) atomicExch(&g_is32, 1);
    }
}

// ---------------------------------------------------------------------------
// 2. histogram of dst (scalar int atomics only)
// ---------------------------------------------------------------------------
__global__ void hist_kernel(const void* __restrict__ ei, int E) {
    int e = blockIdx.x * blockDim.x + threadIdx.x;
    if (e >= E) return;
    int d = read_idx(ei, E, 1, e, g_is32);
    atomicAdd(&g_count[d], 1);
}

// ---------------------------------------------------------------------------
// 3a. scan phase A: per-block reduction of counts -> g_partial[b]
// ---------------------------------------------------------------------------
__global__ void scanA_kernel() {
    __shared__ int sh[32];
    int i = blockIdx.x * SCAN_TPB + threadIdx.x;
    int v = (i < N_NODES) ? g_count[i] : 0;
    #pragma unroll
    for (int o = 16; o > 0; o >>= 1) v += __shfl_down_sync(0xFFFFFFFFu, v, o);
    int lane = threadIdx.x & 31, warp = threadIdx.x >> 5;
    if (lane == 0) sh[warp] = v;
    __syncthreads();
    if (warp == 0) {
        v = (lane < SCAN_TPB / 32) ? sh[lane] : 0;
        #pragma unroll
        for (int o = 16; o > 0; o >>= 1) v += __shfl_down_sync(0xFFFFFFFFu, v, o);
        if (lane == 0) g_partial[blockIdx.x] = v;
    }
}

// ---------------------------------------------------------------------------
// 3b. scan phase C: each block inlines the scan of the 98 partials, then
//     local scan. Writes rowstart, cursor (=rowstart), dinv.
// ---------------------------------------------------------------------------
__global__ void scanC_kernel() {
    __shared__ int sh[SCAN_TPB];
    __shared__ int off[128];
    int t = threadIdx.x;

    int raw = 0;
    if (t < 128) {
        raw = (t < SCAN_NB) ? g_partial[t] : 0;
        off[t] = raw;
    }
    __syncthreads();
    for (int o = 1; o < 128; o <<= 1) {
        int u = 0;
        if (t < 128 && t >= o) u = off[t - o];
        __syncthreads();
        if (t < 128) off[t] += u;
        __syncthreads();
    }
    __shared__ int blk_off, total;
    if (t == blockIdx.x) blk_off = off[t] - raw;
    if (t == 127) total = off[127];
    __syncthreads();

    int i = blockIdx.x * SCAN_TPB + t;
    int c = (i < N_NODES) ? g_count[i] : 0;
    sh[t] = c;
    __syncthreads();
    for (int o = 1; o < SCAN_TPB; o <<= 1) {
        int u = (t >= o) ? sh[t - o] : 0;
        __syncthreads();
        sh[t] += u;
        __syncthreads();
    }
    if (i < N_NODES) {
        int rs = blk_off + sh[t] - c;                 // exclusive
        g_rowstart[i] = rs;
        g_cursor[i]   = rs;                           // seed fill cursor
        g_dinv[i] = rsqrtf((float)c + 1.0f);
    }
    if (blockIdx.x == 0 && t == 0) g_rowstart[N_NODES] = total;
}

// ---------------------------------------------------------------------------
// 4. fill adjacency (src ids grouped by dst; cursor pre-seeded to rowstart)
// ---------------------------------------------------------------------------
__global__ void fill_kernel(const void* __restrict__ ei, int E) {
    int e = blockIdx.x * blockDim.x + threadIdx.x;
    if (e >= E) return;
    int is32 = g_is32;
    int sidx = read_idx(ei, E, 0, e, is32);
    int d    = read_idx(ei, E, 1, e, is32);
    int pos = atomicAdd(&g_cursor[d], 1);   // absolute position
    g_adj[pos] = sidx;
}

// ---------------------------------------------------------------------------
// 5. g_h = fp16(x @ W1)   (N x 128) @ (128 x 64); 32 rows/block, 256 threads.
// ---------------------------------------------------------------------------
__global__ void gemm1_kernel(const float* __restrict__ x,
                             const float* __restrict__ W1) {
    __shared__ float Ws[F_IN * F_HID];   // 32 KB
    __shared__ float xs[32][F_IN];       // 16 KB

    int tid = threadIdx.x;               // 0..255
    for (int i = tid; i < F_IN * F_HID; i += 256) Ws[i] = W1[i];

    int row0 = blockIdx.x * 32;
    for (int i = tid; i < 32 * F_IN; i += 256) {
        int r = i >> 7, k = i & 127;
        int row = row0 + r;
        xs[r][k] = (row < N_NODES) ? x[(size_t)row * F_IN + k] : 0.0f;
    }
    __syncthreads();

    int col = tid & 63;
    int rg  = tid >> 6;                  // 0..3 -> rows rg*8 .. rg*8+7
    int rbase = rg * 8;
    float acc[8];
    #pragma unroll
    for (int r = 0; r < 8; r++) acc[r] = 0.0f;

#pragma unroll
    for (int k = 0; k < F_IN; k++) {
        float w = Ws[k * F_HID + col];
        #pragma unroll
        for (int r = 0; r < 8; r++) acc[r] = fmaf(xs[rbase + r][k], w, acc[r]);
    }
    #pragma unroll
    for (int r = 0; r < 8; r++) {
        int row = row0 + rbase + r;
        if (row < N_NODES) g_h[(size_t)row * F_HID + col] = __float2half(acc[r]);
    }
}

// ---------------------------------------------------------------------------
// aggregation core: 16 lanes per node, lane owns 4 fp16 features (uint2 = 8B).
// A full node row = 128B = one cache line. fp32 accumulation.
// Edge loop unrolled x4 (proven structure).
// ---------------------------------------------------------------------------
__device__ __forceinline__ float4 agg_node(const __half* __restrict__ in,
                                           int node, int fo) {
    float di = g_dinv[node];
    float4 v = h4_to_f4(*reinterpret_cast<const uint2*>(&in[(size_t)node * F_HID + fo]));
    float dd = di * di;
    float ax = dd * v.x, ay = dd * v.y, az = dd * v.z, aw = dd * v.w;

    int beg = g_rowstart[node];
    int end = g_rowstart[node + 1];

    int j = beg;
    for (; j + 3 < end; j += 4) {
        int s0 = g_adj[j + 0];
        int s1 = g_adj[j + 1];
        int s2 = g_adj[j + 2];
        int s3 = g_adj[j + 3];
        float c0 = g_dinv[s0] * di;
        float c1 = g_dinv[s1] * di;
        float c2 = g_dinv[s2] * di;
        float c3 = g_dinv[s3] * di;
        uint2 r0 = *reinterpret_cast<const uint2*>(&in[(size_t)s0 * F_HID + fo]);
        uint2 r1 = *reinterpret_cast<const uint2*>(&in[(size_t)s1 * F_HID + fo]);
        uint2 r2 = *reinterpret_cast<const uint2*>(&in[(size_t)s2 * F_HID + fo]);
        uint2 r3 = *reinterpret_cast<const uint2*>(&in[(size_t)s3 * F_HID + fo]);
        float4 h0 = h4_to_f4(r0);
        float4 h1 = h4_to_f4(r1);
        float4 h2 = h4_to_f4(r2);
        float4 h3 = h4_to_f4(r3);
        ax = fmaf(c0, h0.x, ax); ay = fmaf(c0, h0.y, ay);
        az = fmaf(c0, h0.z, az); aw = fmaf(c0, h0.w, aw);
        ax = fmaf(c1, h1.x, ax); ay = fmaf(c1, h1.y, ay);
        az = fmaf(c1, h1.z, az); aw = fmaf(c1, h1.w, aw);
        ax = fmaf(c2, h2.x, ax); ay = fmaf(c2, h2.y, ay);
        az = fmaf(c2, h2.z, az); aw = fmaf(c2, h2.w, aw);
        ax = fmaf(c3, h3.x, ax); ay = fmaf(c3, h3.y, ay);
        az = fmaf(c3, h3.z, az); aw = fmaf(c3, h3.w, aw);
    }
    for (; j < end; j++) {
        int s = g_adj[j];
        float c = g_dinv[s] * di;
        float4 hv = h4_to_f4(*reinterpret_cast<const uint2*>(&in[(size_t)s * F_HID + fo]));
        ax = fmaf(c, hv.x, ax); ay = fmaf(c, hv.y, ay);
        az = fmaf(c, hv.z, az); aw = fmaf(c, hv.w, aw);
    }
    return make_float4(ax, ay, az, aw);
}

// ---------------------------------------------------------------------------
// 6. pass-1 aggregate + bias + relu -> g_h2 (fp16)
// ---------------------------------------------------------------------------
__global__ void agg1_kernel(const float* __restrict__ b1) {
    int tid    = threadIdx.x;            // 256 threads = 16 nodes/block
    int group  = tid >> 4;
    int lane16 = tid & 15;
    int node = blockIdx.x * 16 + group;
    if (node >= N_NODES) return;

    int fo = lane16 * 4;
    float4 a = agg_node(g_h, node, fo);

    float4 bb = *reinterpret_cast<const float4*>(&b1[fo]);
    a.x += bb.x; a.y += bb.y; a.z += bb.z; a.w += bb.w;
    a.x = a.x > 0.f ? a.x : 0.f;
    a.y = a.y > 0.f ? a.y : 0.f;
    a.z = a.z > 0.f ? a.z : 0.f;
    a.w = a.w > 0.f ? a.w : 0.f;
    *reinterpret_cast<uint2*>(&g_h2[(size_t)node * F_HID + fo]) = f4_to_h4(a);
}

// ---------------------------------------------------------------------------
// 7. FUSED pass-2 aggregate + dual output GEMM.
// ---------------------------------------------------------------------------
__global__ void agg2_out_kernel(const float* __restrict__ Wmu,
                                const float* __restrict__ bmu,
                                const float* __restrict__ Wls,
                                const float* __restrict__ bls,
                                float* __restrict__ out) {
    __shared__ float Wm[F_HID * F_OUT];  // 8 KB
    __shared__ float Wl[F_HID * F_OUT];  // 8 KB
    __shared__ float hs[16][F_HID];      // 4 KB

    int tid = threadIdx.x;               // 0..255
    for (int i = tid; i < F_HID * F_OUT; i += 256) { Wm[i] = Wmu[i]; Wl[i] = Wls[i]; }

    int node0 = blockIdx.x * 16;

    // Phase A: aggregation (16 lanes per node, 4 fp16 features per lane)
    {
        int group  = tid >> 4;
        int lane16 = tid & 15;
        int node = node0 + group;
        if (node < N_NODES) {
            int fo = lane16 * 4;
            float4 a = agg_node(g_h2, node, fo);
            *reinterpret_cast<float4*>(&hs[group][fo]) = a;
        }
    }
    __syncthreads();

    // Phase B: dual GEMM, warp per node (2 nodes per warp via stride-8 loop)
    int warp = tid >> 5, lane = tid & 31;
    float bm = bmu[lane];
    float bl = bls[lane];
    #pragma unroll
    for (int nn = warp; nn < 16; nn += 8) {
        int node = node0 + nn;
        if (node >= N_NODES) continue;
        float am = bm;
        float al = bl;
        #pragma unroll
        for (int f = 0; f < F_HID; f++) {
            float hv = hs[nn][f];
            am = fmaf(hv, Wm[f * F_OUT + lane], am);
            al = fmaf(hv, Wl[f * F_OUT + lane], al);
        }
        out[(size_t)node * F_OUT + lane] = am;
        out[(size_t)N_NODES * F_OUT + (size_t)node * F_OUT + lane] = al;
    }
}

// ---------------------------------------------------------------------------
// launch — cudaStreamPerThread main line; gemm1 forked onto a second captured
// stream (event fork/join) so it overlaps the whole CSR-build chain.
// Streams/events created once on first (non-capture) call, reused thereafter;
// the recorded work is identical on every call.
// ---------------------------------------------------------------------------
extern "C" void kernel_launch(void* const* d_in, const int* in_sizes, int n_in,
                              void* d_out, int out_size) {
    const float* x   = (const float*)d_in[0];
    const void*  ei  = d_in[1];                    // [2, E], int32 OR int64
    const float* W1  = (const float*)d_in[2];
    const float* b1  = (const float*)d_in[3];
    const float* Wmu = (const float*)d_in[4];
    const float* bmu = (const float*)d_in[5];
    const float* Wls = (const float*)d_in[6];
    const float* bls = (const float*)d_in[7];
    float*       out = (float*)d_out;

    const int E = in_sizes[1] / 2;
    const int T = 256;
    cudaStream_t s = cudaStreamPerThread;

    static cudaStream_t s2 = nullptr;
    static cudaEvent_t evFork = nullptr, evJoin = nullptr;
    if (s2 == nullptr) {
        cudaStreamCreateWithFlags(&s2, cudaStreamNonBlocking);
        cudaEventCreateWithFlags(&evFork, cudaEventDisableTiming);
        cudaEventCreateWithFlags(&evJoin, cudaEventDisableTiming);
    }

    // main chain start
    initdetect_kernel<<<(N_NODES + T - 1) / T, T, 0, s>>>(
        (const unsigned long long*)ei, E);

    // fork: gemm1 is independent of the CSR chain
    cudaEventRecord(evFork, s);
    cudaStreamWaitEvent(s2, evFork, 0);
    gemm1_kernel<<<(N_NODES + 31) / 32, T, 0, s2>>>(x, W1);
    cudaEventRecord(evJoin, s2);

    // CSR chain continues on main stream
    hist_kernel<<<(E + T - 1) / T, T, 0, s>>>(ei, E);
    scanA_kernel<<<SCAN_NB, SCAN_TPB, 0, s>>>();
    scanC_kernel<<<SCAN_NB, SCAN_TPB, 0, s>>>();
    fill_kernel<<<(E + T - 1) / T, T, 0, s>>>(ei, E);

    // join: agg1 needs both g_h (gemm1) and the CSR
    cudaStreamWaitEvent(s, evJoin, 0);
    agg1_kernel<<<(N_NODES + 15) / 16, T, 0, s>>>(b1);
    agg2_out_kernel<<<(N_NODES + 15) / 16, T, 0, s>>>(Wmu, bmu, Wls, bls, out);
}